// round 4
// baseline (speedup 1.0000x reference)
#include <cuda_runtime.h>

#define N_MAX   100000
#define NE_MAX  3200000
#define FIN     512
#define HID     16
#define NC      7
#define H2      8
#define NB      256            // nodes per block in gemm1
#define TPB     256            // threads per block in gemm1
#define KC      32             // k-chunk staged in smem
#define NCHUNK  (FIN / KC)     // 16
#define SB      256            // scan block
#define NBLK    ((N_MAX + SB - 1) / SB)   // 391

// -------- scratch --------
__device__ float g_dinv[N_MAX];
__device__ int   g_degE[N_MAX];
__device__ int   g_off [N_MAX + 1];
__device__ int   g_cur [N_MAX];
__device__ int   g_srcs[NE_MAX];
__device__ int   g_bsum [NBLK];
__device__ int   g_bscan[NBLK];
__device__ float g_xs  [N_MAX * HID];   // dinv * (x @ W1)
__device__ float g_agg1[N_MAX * HID];
__device__ float g_hs  [N_MAX * H2];    // dinv * (relu(h1) @ W2)
__device__ float g_agg2[N_MAX * H2];

__device__ __forceinline__ unsigned long long pack2(float a, float b) {
    unsigned long long r;
    asm("mov.b64 %0,{%1,%2};" : "=l"(r) : "f"(a), "f"(b));
    return r;
}
__device__ __forceinline__ void ffma2(unsigned long long& d,
                                      unsigned long long a, unsigned long long b) {
    asm("fma.rn.f32x2 %0,%1,%2,%0;" : "+l"(d) : "l"(a), "l"(b));
}
__device__ __forceinline__ float2 unpack2(unsigned long long v) {
    float2 u;
    asm("mov.b64 {%0,%1},%2;" : "=f"(u.x), "=f"(u.y) : "l"(v));
    return u;
}

// ================= CSR build =================
__global__ void k_zero(int n) {
    int i = blockIdx.x * blockDim.x + threadIdx.x;
    if (i < n) g_degE[i] = 0;
}
__global__ void k_degE(const int* __restrict__ col, int ne) {
    int e = blockIdx.x * blockDim.x + threadIdx.x;
    if (e < ne) atomicAdd(&g_degE[col[e]], 1);
}
__global__ void k_dinv(int n) {
    int i = blockIdx.x * blockDim.x + threadIdx.x;
    if (i < n) g_dinv[i] = rsqrtf((float)g_degE[i] + 1.0f);
}
__global__ void k_bsum(int n) {
    __shared__ int s[SB];
    int i = blockIdx.x * SB + threadIdx.x;
    s[threadIdx.x] = (i < n) ? g_degE[i] : 0;
    __syncthreads();
#pragma unroll
    for (int d = SB / 2; d > 0; d >>= 1) {
        if (threadIdx.x < d) s[threadIdx.x] += s[threadIdx.x + d];
        __syncthreads();
    }
    if (threadIdx.x == 0) g_bsum[blockIdx.x] = s[0];
}
__global__ void k_bscan(int nb) {   // single block, 512 threads
    __shared__ int s[512];
    int t = threadIdx.x;
    int v = (t < nb) ? g_bsum[t] : 0;
    s[t] = v;
    __syncthreads();
    for (int d = 1; d < 512; d <<= 1) {
        int u = (t >= d) ? s[t - d] : 0;
        __syncthreads();
        s[t] += u;
        __syncthreads();
    }
    if (t < nb) g_bscan[t] = s[t] - v;   // exclusive
}
__global__ void k_off(int n) {
    __shared__ int s[SB];
    int i = blockIdx.x * SB + threadIdx.x;
    int v = (i < n) ? g_degE[i] : 0;
    s[threadIdx.x] = v;
    __syncthreads();
    for (int d = 1; d < SB; d <<= 1) {
        int u = (threadIdx.x >= d) ? s[threadIdx.x - d] : 0;
        __syncthreads();
        s[threadIdx.x] += u;
        __syncthreads();
    }
    if (i < n) {
        int o = g_bscan[blockIdx.x] + s[threadIdx.x] - v;
        g_off[i] = o;
        g_cur[i] = o;
        if (i == n - 1) g_off[n] = o + v;
    }
}
__global__ void k_scatter(const int* __restrict__ row,
                          const int* __restrict__ col, int ne) {
    int e = blockIdx.x * blockDim.x + threadIdx.x;
    if (e >= ne) return;
    int c = col[e];
    int slot = atomicAdd(&g_cur[c], 1);
    g_srcs[slot] = row[e];
}

// ======== xs = dinv * (x @ W1): 1 node/thread, reg-prefetch, KC=32 ========
__global__ void __launch_bounds__(TPB)
k_gemm1(const float* __restrict__ x, const float* __restrict__ W1, int n) {
    __shared__ float sX[NB * (KC + 1)];   // 256*33*4 = 33792 B
    __shared__ float sW[KC * HID];        // 2048 B
    const int tid  = threadIdx.x;
    const int base = blockIdx.x * NB;

    unsigned long long acc[HID / 2];
#pragma unroll
    for (int p = 0; p < HID / 2; p++) acc[p] = 0ull;

    // staging map: 2048 float4 per chunk; t = tid + i*TPB, r = t>>3, c4 = t&7
    const int sr  = tid >> 3;
    const int sc4 = tid & 7;

    float4 px[8];
    float4 pw;
#pragma unroll
    for (int i = 0; i < 8; i++) {
        int gn = base + sr + i * 32;
        px[i] = (gn < n) ? __ldg((const float4*)(x + (size_t)gn * FIN) + sc4)
                         : make_float4(0.f, 0.f, 0.f, 0.f);
    }
    if (tid < KC * HID / 4) pw = __ldg((const float4*)W1 + tid);

    for (int c = 0; c < NCHUNK; c++) {
        __syncthreads();
#pragma unroll
        for (int i = 0; i < 8; i++) {
            float* s = &sX[(sr + i * 32) * (KC + 1) + sc4 * 4];
            s[0] = px[i].x; s[1] = px[i].y; s[2] = px[i].z; s[3] = px[i].w;
        }
        if (tid < KC * HID / 4) ((float4*)sW)[tid] = pw;
        __syncthreads();

        if (c + 1 < NCHUNK) {
            int kc = (c + 1) * KC;
#pragma unroll
            for (int i = 0; i < 8; i++) {
                int gn = base + sr + i * 32;
                px[i] = (gn < n)
                      ? __ldg((const float4*)(x + (size_t)gn * FIN + kc) + sc4)
                      : make_float4(0.f, 0.f, 0.f, 0.f);
            }
            if (tid < KC * HID / 4)
                pw = __ldg((const float4*)(W1 + kc * HID) + tid);
        }

        const float* xr = &sX[tid * (KC + 1)];
#pragma unroll
        for (int k = 0; k < KC; k++) {
            unsigned long long xx = pack2(xr[k], xr[k]);
            const ulonglong2* wr = (const ulonglong2*)(&sW[k * HID]);
#pragma unroll
            for (int p = 0; p < HID / 4; p++) {
                ulonglong2 w = wr[p];
                ffma2(acc[2 * p],     w.x, xx);
                ffma2(acc[2 * p + 1], w.y, xx);
            }
        }
    }

    int n0 = base + tid;
    if (n0 < n) {
        float d = g_dinv[n0];
        float4* o = (float4*)(&g_xs[(size_t)n0 * HID]);
#pragma unroll
        for (int p = 0; p < HID / 4; p++) {
            float2 a = unpack2(acc[2 * p]), b = unpack2(acc[2 * p + 1]);
            o[p] = make_float4(d * a.x, d * a.y, d * b.x, d * b.y);
        }
    }
}

// ======== layer-1 aggregation: warp per node, CSR gather + shfl reduce ====
__global__ void k_agg1w(int n) {
    int w = (blockIdx.x * blockDim.x + threadIdx.x) >> 5;
    if (w >= n) return;
    int lane = threadIdx.x & 31;
    int q = lane & 3, eq = lane >> 2;      // 8 edge-lanes x 4 quads
    int s0 = g_off[w], s1 = g_off[w + 1];
    float4 a = make_float4(0.f, 0.f, 0.f, 0.f);
    for (int e = s0 + eq; e < s1; e += 8) {
        int src = __ldg(&g_srcs[e]);
        float4 v = *(const float4*)(&g_xs[(size_t)src * HID + q * 4]);
        a.x += v.x; a.y += v.y; a.z += v.z; a.w += v.w;
    }
#pragma unroll
    for (int d = 4; d < 32; d <<= 1) {
        a.x += __shfl_xor_sync(0xffffffffu, a.x, d);
        a.y += __shfl_xor_sync(0xffffffffu, a.y, d);
        a.z += __shfl_xor_sync(0xffffffffu, a.z, d);
        a.w += __shfl_xor_sync(0xffffffffu, a.w, d);
    }
    if (lane < 4) *(float4*)(&g_agg1[(size_t)w * HID + q * 4]) = a;
}

// ---- h1 = relu(dinv*(agg1 + xs) + b1); hs = dinv * (h1 @ W2) ----
__global__ void k_h1(const float* __restrict__ b1,
                     const float* __restrict__ W2, int n) {
    __shared__ float sW2[HID * NC];
    __shared__ float sb1[HID];
    if (threadIdx.x < HID * NC) sW2[threadIdx.x] = W2[threadIdx.x];
    if (threadIdx.x < HID)      sb1[threadIdx.x] = b1[threadIdx.x];
    __syncthreads();

    int i = blockIdx.x * blockDim.x + threadIdx.x;
    if (i >= n) return;

    float d = g_dinv[i];
    float h[HID];
#pragma unroll
    for (int j = 0; j < HID; j++) {
        float v = d * (g_agg1[(size_t)i * HID + j] + g_xs[(size_t)i * HID + j]) + sb1[j];
        h[j] = v > 0.f ? v : 0.f;
    }
    float y[H2];
#pragma unroll
    for (int j = 0; j < H2; j++) y[j] = 0.f;
#pragma unroll
    for (int k = 0; k < HID; k++) {
        float hk = h[k];
#pragma unroll
        for (int j = 0; j < NC; j++) y[j] += hk * sW2[k * NC + j];
    }
    float4* o = (float4*)(&g_hs[(size_t)i * H2]);
    o[0] = make_float4(d * y[0], d * y[1], d * y[2], d * y[3]);
    o[1] = make_float4(d * y[4], d * y[5], d * y[6], 0.f);
}

// ======== layer-2 aggregation: warp per node ====
__global__ void k_agg2w(int n) {
    int w = (blockIdx.x * blockDim.x + threadIdx.x) >> 5;
    if (w >= n) return;
    int lane = threadIdx.x & 31;
    int q = lane & 1, eq = lane >> 1;      // 16 edge-lanes x 2 quads
    int s0 = g_off[w], s1 = g_off[w + 1];
    float4 a = make_float4(0.f, 0.f, 0.f, 0.f);
    for (int e = s0 + eq; e < s1; e += 16) {
        int src = __ldg(&g_srcs[e]);
        float4 v = *(const float4*)(&g_hs[(size_t)src * H2 + q * 4]);
        a.x += v.x; a.y += v.y; a.z += v.z; a.w += v.w;
    }
#pragma unroll
    for (int d = 2; d < 32; d <<= 1) {
        a.x += __shfl_xor_sync(0xffffffffu, a.x, d);
        a.y += __shfl_xor_sync(0xffffffffu, a.y, d);
        a.z += __shfl_xor_sync(0xffffffffu, a.z, d);
        a.w += __shfl_xor_sync(0xffffffffu, a.w, d);
    }
    if (lane < 2) *(float4*)(&g_agg2[(size_t)w * H2 + q * 4]) = a;
}

// ---- out = dinv*(agg2 + hs) + b2 ----
__global__ void k_out(float* __restrict__ out, const float* __restrict__ b2, int n) {
    int i = blockIdx.x * blockDim.x + threadIdx.x;
    if (i >= n) return;
    float d = g_dinv[i];
#pragma unroll
    for (int j = 0; j < NC; j++)
        out[(size_t)i * NC + j] =
            d * (g_agg2[(size_t)i * H2 + j] + g_hs[(size_t)i * H2 + j]) + __ldg(&b2[j]);
}

extern "C" void kernel_launch(void* const* d_in, const int* in_sizes, int n_in,
                              void* d_out, int out_size) {
    const float* x  = (const float*)d_in[0];
    const int*   ei = (const int*)  d_in[1];
    const float* W1 = (const float*)d_in[2];
    const float* b1 = (const float*)d_in[3];
    const float* W2 = (const float*)d_in[4];
    const float* b2 = (const float*)d_in[5];

    int n  = in_sizes[0] / FIN;
    int ne = in_sizes[1] / 2;
    const int* row = ei;
    const int* col = ei + ne;
    int nb = (n + SB - 1) / SB;

    // CSR build
    k_zero   <<<(n + 255) / 256, 256>>>(n);
    k_degE   <<<(ne + 255) / 256, 256>>>(col, ne);
    k_dinv   <<<(n + 255) / 256, 256>>>(n);
    k_bsum   <<<nb, SB>>>(n);
    k_bscan  <<<1, 512>>>(nb);
    k_off    <<<nb, SB>>>(n);
    k_scatter<<<(ne + 255) / 256, 256>>>(row, col, ne);

    // GCN layers
    k_gemm1<<<(n + NB - 1) / NB, TPB>>>(x, W1, n);
    k_agg1w<<<(n * 32 + 255) / 256, 256>>>(n);
    k_h1   <<<(n + 255) / 256, 256>>>(b1, W2, n);
    k_agg2w<<<(n * 32 + 255) / 256, 256>>>(n);
    k_out  <<<(n + 255) / 256, 256>>>((float*)d_out, b2, n);
}

// round 5
// speedup vs baseline: 1.0891x; 1.0891x over previous
#include <cuda_runtime.h>

#define N_MAX   100000
#define FIN     512
#define HID     16
#define NC      7
#define H2      8
#define NB      256            // nodes per block in gemm1
#define TPB     256            // threads per block in gemm1
#define KC      32             // k-chunk staged in smem
#define NCHUNK  (FIN / KC)     // 16

// -------- scratch --------
__device__ float g_dinv[N_MAX];
__device__ float g_deg [N_MAX];
__device__ float g_xs  [N_MAX * HID];   // dinv * (x @ W1)
__device__ float g_agg1[N_MAX * HID];
__device__ float g_hs  [N_MAX * H2];    // dinv * (relu(h1) @ W2)
__device__ float g_agg2[N_MAX * H2];

__device__ __forceinline__ void red_add_v4(float* p, float4 v) {
    asm volatile("red.global.add.v4.f32 [%0], {%1,%2,%3,%4};"
                 :: "l"(p), "f"(v.x), "f"(v.y), "f"(v.z), "f"(v.w)
                 : "memory");
}
__device__ __forceinline__ unsigned long long pack2(float a, float b) {
    unsigned long long r;
    asm("mov.b64 %0,{%1,%2};" : "=l"(r) : "f"(a), "f"(b));
    return r;
}
__device__ __forceinline__ void ffma2(unsigned long long& d,
                                      unsigned long long a, unsigned long long b) {
    asm("fma.rn.f32x2 %0,%1,%2,%0;" : "+l"(d) : "l"(a), "l"(b));
}
__device__ __forceinline__ float2 unpack2(unsigned long long v) {
    float2 u;
    asm("mov.b64 {%0,%1},%2;" : "=f"(u.x), "=f"(u.y) : "l"(v));
    return u;
}

// -------- init: zero accumulators, deg = 1 (self loop) --------
__global__ void k_init(int n) {
    int stride = gridDim.x * blockDim.x;
    int t0 = blockIdx.x * blockDim.x + threadIdx.x;
    for (int t = t0; t < n * HID; t += stride) g_agg1[t] = 0.f;
    for (int t = t0; t < n * H2;  t += stride) g_agg2[t] = 0.f;
    for (int t = t0; t < n;       t += stride) g_deg[t]  = 1.f;
}

__global__ void k_deg(const int* __restrict__ col, int ne) {
    int e = blockIdx.x * blockDim.x + threadIdx.x;
    if (e < ne) atomicAdd(&g_deg[col[e]], 1.0f);
}

__global__ void k_dinv(int n) {
    int i = blockIdx.x * blockDim.x + threadIdx.x;
    if (i < n) g_dinv[i] = rsqrtf(g_deg[i]);
}

// ======== xs = dinv * (x @ W1): 1 node/thread, reg-prefetch, KC=32 ========
__global__ void __launch_bounds__(TPB)
k_gemm1(const float* __restrict__ x, const float* __restrict__ W1, int n) {
    __shared__ float sX[NB * (KC + 1)];   // 256*33*4 = 33792 B
    __shared__ float sW[KC * HID];        // 2048 B
    const int tid  = threadIdx.x;
    const int base = blockIdx.x * NB;

    unsigned long long acc[HID / 2];
#pragma unroll
    for (int p = 0; p < HID / 2; p++) acc[p] = 0ull;

    // staging map: 2048 float4 per chunk; t = tid + i*TPB, r = t>>3, c4 = t&7
    const int sr  = tid >> 3;
    const int sc4 = tid & 7;

    float4 px[8];
    float4 pw;
#pragma unroll
    for (int i = 0; i < 8; i++) {
        int gn = base + sr + i * 32;
        px[i] = (gn < n) ? __ldg((const float4*)(x + (size_t)gn * FIN) + sc4)
                         : make_float4(0.f, 0.f, 0.f, 0.f);
    }
    if (tid < KC * HID / 4) pw = __ldg((const float4*)W1 + tid);

    for (int c = 0; c < NCHUNK; c++) {
        __syncthreads();
#pragma unroll
        for (int i = 0; i < 8; i++) {
            float* s = &sX[(sr + i * 32) * (KC + 1) + sc4 * 4];
            s[0] = px[i].x; s[1] = px[i].y; s[2] = px[i].z; s[3] = px[i].w;
        }
        if (tid < KC * HID / 4) ((float4*)sW)[tid] = pw;
        __syncthreads();

        if (c + 1 < NCHUNK) {
            int kc = (c + 1) * KC;
#pragma unroll
            for (int i = 0; i < 8; i++) {
                int gn = base + sr + i * 32;
                px[i] = (gn < n)
                      ? __ldg((const float4*)(x + (size_t)gn * FIN + kc) + sc4)
                      : make_float4(0.f, 0.f, 0.f, 0.f);
            }
            if (tid < KC * HID / 4)
                pw = __ldg((const float4*)(W1 + kc * HID) + tid);
        }

        const float* xr = &sX[tid * (KC + 1)];
#pragma unroll
        for (int k = 0; k < KC; k++) {
            unsigned long long xx = pack2(xr[k], xr[k]);
            const ulonglong2* wr = (const ulonglong2*)(&sW[k * HID]);
#pragma unroll
            for (int p = 0; p < HID / 4; p++) {
                ulonglong2 w = wr[p];
                ffma2(acc[2 * p],     w.x, xx);
                ffma2(acc[2 * p + 1], w.y, xx);
            }
        }
    }

    int n0 = base + tid;
    if (n0 < n) {
        float d = g_dinv[n0];
        float4* o = (float4*)(&g_xs[(size_t)n0 * HID]);
#pragma unroll
        for (int p = 0; p < HID / 4; p++) {
            float2 a = unpack2(acc[2 * p]), b = unpack2(acc[2 * p + 1]);
            o[p] = make_float4(d * a.x, d * a.y, d * b.x, d * b.y);
        }
    }
}

// -------- layer-1 edge aggregation: pure gather + red (norm folded) --------
__global__ void k_agg1(const int* __restrict__ row,
                       const int* __restrict__ col, int ne) {
    int t = blockIdx.x * blockDim.x + threadIdx.x;
    int e = t >> 2, q = t & 3;
    if (e >= ne) return;
    int r = __ldg(&row[e]);
    int c = __ldg(&col[e]);
    float4 v = *(const float4*)(&g_xs[(size_t)r * HID + q * 4]);
    red_add_v4(&g_agg1[(size_t)c * HID + q * 4], v);
}

// ---- h1 = relu(dinv*(agg1 + xs) + b1); hs = dinv * (h1 @ W2) ----
__global__ void k_h1(const float* __restrict__ b1,
                     const float* __restrict__ W2, int n) {
    __shared__ float sW2[HID * NC];
    __shared__ float sb1[HID];
    if (threadIdx.x < HID * NC) sW2[threadIdx.x] = W2[threadIdx.x];
    if (threadIdx.x < HID)      sb1[threadIdx.x] = b1[threadIdx.x];
    __syncthreads();

    int i = blockIdx.x * blockDim.x + threadIdx.x;
    if (i >= n) return;

    float d = g_dinv[i];
    float h[HID];
#pragma unroll
    for (int j = 0; j < HID; j++) {
        float v = d * (g_agg1[(size_t)i * HID + j] + g_xs[(size_t)i * HID + j]) + sb1[j];
        h[j] = v > 0.f ? v : 0.f;
    }
    float y[H2];
#pragma unroll
    for (int j = 0; j < H2; j++) y[j] = 0.f;
#pragma unroll
    for (int k = 0; k < HID; k++) {
        float hk = h[k];
#pragma unroll
        for (int j = 0; j < NC; j++) y[j] += hk * sW2[k * NC + j];
    }
    float4* o = (float4*)(&g_hs[(size_t)i * H2]);
    o[0] = make_float4(d * y[0], d * y[1], d * y[2], d * y[3]);
    o[1] = make_float4(d * y[4], d * y[5], d * y[6], 0.f);
}

// -------- layer-2 edge aggregation --------
__global__ void k_agg2(const int* __restrict__ row,
                       const int* __restrict__ col, int ne) {
    int t = blockIdx.x * blockDim.x + threadIdx.x;
    int e = t >> 1, q = t & 1;
    if (e >= ne) return;
    int r = __ldg(&row[e]);
    int c = __ldg(&col[e]);
    float4 v = *(const float4*)(&g_hs[(size_t)r * H2 + q * 4]);
    red_add_v4(&g_agg2[(size_t)c * H2 + q * 4], v);
}

// ---- out = dinv*(agg2 + hs) + b2 ----
__global__ void k_out(float* __restrict__ out, const float* __restrict__ b2, int n) {
    int i = blockIdx.x * blockDim.x + threadIdx.x;
    if (i >= n) return;
    float d = g_dinv[i];
#pragma unroll
    for (int j = 0; j < NC; j++)
        out[(size_t)i * NC + j] =
            d * (g_agg2[(size_t)i * H2 + j] + g_hs[(size_t)i * H2 + j]) + __ldg(&b2[j]);
}

extern "C" void kernel_launch(void* const* d_in, const int* in_sizes, int n_in,
                              void* d_out, int out_size) {
    const float* x  = (const float*)d_in[0];
    const int*   ei = (const int*)  d_in[1];
    const float* W1 = (const float*)d_in[2];
    const float* b1 = (const float*)d_in[3];
    const float* W2 = (const float*)d_in[4];
    const float* b2 = (const float*)d_in[5];

    int n  = in_sizes[0] / FIN;
    int ne = in_sizes[1] / 2;
    const int* row = ei;
    const int* col = ei + ne;

    k_init <<<148 * 8, 256>>>(n);
    k_deg  <<<(ne + 255) / 256, 256>>>(col, ne);
    k_dinv <<<(n + 255) / 256, 256>>>(n);
    k_gemm1<<<(n + NB - 1) / NB, TPB>>>(x, W1, n);
    k_agg1 <<<((ne * 4) + 255) / 256, 256>>>(row, col, ne);
    k_h1   <<<(n + 255) / 256, 256>>>(b1, W2, n);
    k_agg2 <<<((ne * 2) + 255) / 256, 256>>>(row, col, ne);
    k_out  <<<(n + 255) / 256, 256>>>((float*)d_out, b2, n);
}

// round 6
// speedup vs baseline: 1.1475x; 1.0536x over previous
#include <cuda_runtime.h>

#define N_MAX   100000
#define FIN     512
#define HID     16
#define NC      7
#define H2      8
#define NB      256            // nodes per gemm block
#define TPB     128            // threads per gemm block
#define KC      16             // k-chunk staged in smem
#define NCHUNK  (FIN / KC)     // 32
#define DEGB    1024           // deg blocks appended to mega grid

// -------- scratch --------
__device__ float g_dinv[N_MAX];
__device__ float g_deg [N_MAX];
__device__ float g_xs  [N_MAX * HID];   // x @ W1, later scaled by dinv
__device__ float g_agg1[N_MAX * HID];
__device__ float g_hs  [N_MAX * H2];
__device__ float g_agg2[N_MAX * H2];

__device__ __forceinline__ void red_add_v4(float* p, float4 v) {
    asm volatile("red.global.add.v4.f32 [%0], {%1,%2,%3,%4};"
                 :: "l"(p), "f"(v.x), "f"(v.y), "f"(v.z), "f"(v.w)
                 : "memory");
}
__device__ __forceinline__ unsigned long long pack2(float a, float b) {
    unsigned long long r;
    asm("mov.b64 %0,{%1,%2};" : "=l"(r) : "f"(a), "f"(b));
    return r;
}
__device__ __forceinline__ void ffma2(unsigned long long& d,
                                      unsigned long long a, unsigned long long b) {
    asm("fma.rn.f32x2 %0,%1,%2,%0;" : "+l"(d) : "l"(a), "l"(b));
}
__device__ __forceinline__ float2 unpack2(unsigned long long v) {
    float2 u;
    asm("mov.b64 {%0,%1},%2;" : "=f"(u.x), "=f"(u.y) : "l"(v));
    return u;
}

// -------- pre: zero accumulators, deg = 1 (self loop) --------
__global__ void k_pre(int n) {
    int stride = gridDim.x * blockDim.x;
    int t0 = blockIdx.x * blockDim.x + threadIdx.x;
    for (int t = t0; t < n * HID; t += stride) g_agg1[t] = 0.f;
    for (int t = t0; t < n * H2;  t += stride) g_agg2[t] = 0.f;
    for (int t = t0; t < n;       t += stride) g_deg[t]  = 1.f;
}

// ======== mega: blocks [0,GB) gemm-raw, blocks [GB,GB+DEGB) deg count ======
__global__ void __launch_bounds__(TPB)
k_mega(const float* __restrict__ x, const float* __restrict__ W1,
       const int* __restrict__ col, int n, int ne, int GB) {
    if (blockIdx.x >= GB) {
        // ---- degree histogram, grid-stride ----
        int t0 = (blockIdx.x - GB) * TPB + threadIdx.x;
        int stride = DEGB * TPB;
        for (int e = t0; e < ne; e += stride)
            atomicAdd(&g_deg[__ldg(&col[e])], 1.0f);
        return;
    }

    // ---- gemm: xs_raw = x @ W1, 2 nodes/thread, swizzled float4 smem ----
    __shared__ float4 sX4[NB * 4];               // 16 KB
    __shared__ float4 sW4[KC * HID / 4];         // 1 KB
    const ulonglong2* sWu = (const ulonglong2*)sW4;
    const int tid  = threadIdx.x;
    const int base = blockIdx.x * NB;

    unsigned long long acc0[HID / 2], acc1[HID / 2];
#pragma unroll
    for (int p = 0; p < HID / 2; p++) { acc0[p] = 0ull; acc1[p] = 0ull; }

    const int sr  = tid >> 2;       // staging base row
    const int c4  = tid & 3;        // staging float4 col (const across i)

    float4 px[8];
    float4 pw;
#pragma unroll
    for (int i = 0; i < 8; i++) {
        int gn = base + sr + i * 32;
        px[i] = (gn < n) ? __ldg((const float4*)(x + (size_t)gn * FIN) + c4)
                         : make_float4(0.f, 0.f, 0.f, 0.f);
    }
    if (tid < KC * HID / 4) pw = __ldg((const float4*)W1 + tid);

    for (int c = 0; c < NCHUNK; c++) {
        __syncthreads();
#pragma unroll
        for (int i = 0; i < 8; i++) {
            int r = sr + i * 32;
            sX4[r * 4 + (c4 ^ ((r >> 1) & 3))] = px[i];
        }
        if (tid < KC * HID / 4) sW4[tid] = pw;
        __syncthreads();

        if (c + 1 < NCHUNK) {
            int kc = (c + 1) * KC;
#pragma unroll
            for (int i = 0; i < 8; i++) {
                int gn = base + sr + i * 32;
                px[i] = (gn < n)
                      ? __ldg((const float4*)(x + (size_t)gn * FIN + kc) + c4)
                      : make_float4(0.f, 0.f, 0.f, 0.f);
            }
            if (tid < KC * HID / 4)
                pw = __ldg((const float4*)(W1 + kc * HID) + tid);
        }

        const int r0 = tid, r1 = tid + TPB;
        const int sw = (r0 >> 1) & 3;   // same for r1 (=r0+128)
#pragma unroll
        for (int kk = 0; kk < 4; kk++) {
            float4 xa = sX4[r0 * 4 + (kk ^ sw)];
            float4 xb = sX4[r1 * 4 + (kk ^ sw)];
            float ea[4] = {xa.x, xa.y, xa.z, xa.w};
            float eb[4] = {xb.x, xb.y, xb.z, xb.w};
#pragma unroll
            for (int e = 0; e < 4; e++) {
                int k = kk * 4 + e;
                unsigned long long xx0 = pack2(ea[e], ea[e]);
                unsigned long long xx1 = pack2(eb[e], eb[e]);
                const ulonglong2* wk = &sWu[k * 4];
#pragma unroll
                for (int p = 0; p < 4; p++) {
                    ulonglong2 w = wk[p];
                    ffma2(acc0[2 * p],     w.x, xx0);
                    ffma2(acc0[2 * p + 1], w.y, xx0);
                    ffma2(acc1[2 * p],     w.x, xx1);
                    ffma2(acc1[2 * p + 1], w.y, xx1);
                }
            }
        }
    }

    int n0 = base + tid, n1 = base + TPB + tid;
    if (n0 < n) {
        float4* o = (float4*)(&g_xs[(size_t)n0 * HID]);
#pragma unroll
        for (int p = 0; p < HID / 4; p++) {
            float2 a = unpack2(acc0[2 * p]), b = unpack2(acc0[2 * p + 1]);
            o[p] = make_float4(a.x, a.y, b.x, b.y);
        }
    }
    if (n1 < n) {
        float4* o = (float4*)(&g_xs[(size_t)n1 * HID]);
#pragma unroll
        for (int p = 0; p < HID / 4; p++) {
            float2 a = unpack2(acc1[2 * p]), b = unpack2(acc1[2 * p + 1]);
            o[p] = make_float4(a.x, a.y, b.x, b.y);
        }
    }
}

// -------- finish: dinv = rsqrt(deg); xs *= dinv --------
__global__ void k_finish(int n) {
    int i = blockIdx.x * blockDim.x + threadIdx.x;
    if (i >= n) return;
    float d = rsqrtf(g_deg[i]);
    g_dinv[i] = d;
    float4* p = (float4*)(&g_xs[(size_t)i * HID]);
#pragma unroll
    for (int j = 0; j < HID / 4; j++) {
        float4 v = p[j];
        v.x *= d; v.y *= d; v.z *= d; v.w *= d;
        p[j] = v;
    }
}

// -------- layer-1 edge aggregation --------
__global__ void k_agg1(const int* __restrict__ row,
                       const int* __restrict__ col, int ne) {
    int t = blockIdx.x * blockDim.x + threadIdx.x;
    int e = t >> 2, q = t & 3;
    if (e >= ne) return;
    int r = __ldg(&row[e]);
    int c = __ldg(&col[e]);
    float4 v = *(const float4*)(&g_xs[(size_t)r * HID + q * 4]);
    red_add_v4(&g_agg1[(size_t)c * HID + q * 4], v);
}

// ---- h1 = relu(dinv*(agg1 + xs) + b1); hs = dinv * (h1 @ W2) ----
__global__ void k_h1(const float* __restrict__ b1,
                     const float* __restrict__ W2, int n) {
    __shared__ float sW2[HID * NC];
    __shared__ float sb1[HID];
    if (threadIdx.x < HID * NC) sW2[threadIdx.x] = W2[threadIdx.x];
    if (threadIdx.x < HID)      sb1[threadIdx.x] = b1[threadIdx.x];
    __syncthreads();

    int i = blockIdx.x * blockDim.x + threadIdx.x;
    if (i >= n) return;

    float d = g_dinv[i];
    float h[HID];
#pragma unroll
    for (int j = 0; j < HID; j++) {
        float v = d * (g_agg1[(size_t)i * HID + j] + g_xs[(size_t)i * HID + j]) + sb1[j];
        h[j] = v > 0.f ? v : 0.f;
    }
    float y[H2];
#pragma unroll
    for (int j = 0; j < H2; j++) y[j] = 0.f;
#pragma unroll
    for (int k = 0; k < HID; k++) {
        float hk = h[k];
#pragma unroll
        for (int j = 0; j < NC; j++) y[j] += hk * sW2[k * NC + j];
    }
    float4* o = (float4*)(&g_hs[(size_t)i * H2]);
    o[0] = make_float4(d * y[0], d * y[1], d * y[2], d * y[3]);
    o[1] = make_float4(d * y[4], d * y[5], d * y[6], 0.f);
}

// -------- layer-2 edge aggregation --------
__global__ void k_agg2(const int* __restrict__ row,
                       const int* __restrict__ col, int ne) {
    int t = blockIdx.x * blockDim.x + threadIdx.x;
    int e = t >> 1, q = t & 1;
    if (e >= ne) return;
    int r = __ldg(&row[e]);
    int c = __ldg(&col[e]);
    float4 v = *(const float4*)(&g_hs[(size_t)r * H2 + q * 4]);
    red_add_v4(&g_agg2[(size_t)c * H2 + q * 4], v);
}

// ---- out = dinv*(agg2 + hs) + b2 ----
__global__ void k_out(float* __restrict__ out, const float* __restrict__ b2, int n) {
    int i = blockIdx.x * blockDim.x + threadIdx.x;
    if (i >= n) return;
    float d = g_dinv[i];
#pragma unroll
    for (int j = 0; j < NC; j++)
        out[(size_t)i * NC + j] =
            d * (g_agg2[(size_t)i * H2 + j] + g_hs[(size_t)i * H2 + j]) + __ldg(&b2[j]);
}

extern "C" void kernel_launch(void* const* d_in, const int* in_sizes, int n_in,
                              void* d_out, int out_size) {
    const float* x  = (const float*)d_in[0];
    const int*   ei = (const int*)  d_in[1];
    const float* W1 = (const float*)d_in[2];
    const float* b1 = (const float*)d_in[3];
    const float* W2 = (const float*)d_in[4];
    const float* b2 = (const float*)d_in[5];

    int n  = in_sizes[0] / FIN;
    int ne = in_sizes[1] / 2;
    const int* row = ei;
    const int* col = ei + ne;
    int GB = (n + NB - 1) / NB;   // 391 gemm blocks

    k_pre   <<<148 * 8, 256>>>(n);
    k_mega  <<<GB + DEGB, TPB>>>(x, W1, col, n, ne, GB);
    k_finish<<<(n + 255) / 256, 256>>>(n);
    k_agg1  <<<((ne * 4) + 255) / 256, 256>>>(row, col, ne);
    k_h1    <<<(n + 255) / 256, 256>>>(b1, W2, n);
    k_agg2  <<<((ne * 2) + 255) / 256, 256>>>(row, col, ne);
    k_out   <<<(n + 255) / 256, 256>>>((float*)d_out, b2, n);
}

// round 7
// speedup vs baseline: 1.3527x; 1.1789x over previous
#include <cuda_runtime.h>

#define N_MAX   100000
#define FIN     512
#define HID     16
#define NC      7
#define H2      8
#define NB      256            // nodes per gemm block
#define TPB     128            // threads per gemm block
#define KC      16             // k floats per chunk
#define NCHUNK  (FIN / KC)     // 32
#define S       3              // pipeline stages
#define DEGB    1024           // deg blocks appended to mega grid
// dynamic smem: S stages of (NB*4 float4 X-tile + 64 float4 W-tile)
#define SMEM_DYN ((S * (NB * 4 + 64)) * 16)

// -------- scratch --------
__device__ float g_dinv[N_MAX];
__device__ float g_deg [N_MAX];
__device__ float g_xs  [N_MAX * HID];   // x @ W1, later scaled by dinv
__device__ float g_agg1[N_MAX * HID];
__device__ float g_hs  [N_MAX * H2];
__device__ float g_agg2[N_MAX * H2];

__device__ __forceinline__ void red_add_v4(float* p, float4 v) {
    asm volatile("red.global.add.v4.f32 [%0], {%1,%2,%3,%4};"
                 :: "l"(p), "f"(v.x), "f"(v.y), "f"(v.z), "f"(v.w)
                 : "memory");
}
__device__ __forceinline__ unsigned long long pack2(float a, float b) {
    unsigned long long r;
    asm("mov.b64 %0,{%1,%2};" : "=l"(r) : "f"(a), "f"(b));
    return r;
}
__device__ __forceinline__ void ffma2(unsigned long long& d,
                                      unsigned long long a, unsigned long long b) {
    asm("fma.rn.f32x2 %0,%1,%2,%0;" : "+l"(d) : "l"(a), "l"(b));
}
__device__ __forceinline__ float2 unpack2(unsigned long long v) {
    float2 u;
    asm("mov.b64 {%0,%1},%2;" : "=f"(u.x), "=f"(u.y) : "l"(v));
    return u;
}
__device__ __forceinline__ void cp16(float4* dst_smem, const float4* src, bool pred) {
    unsigned d = (unsigned)__cvta_generic_to_shared(dst_smem);
    int sz = pred ? 16 : 0;
    asm volatile("cp.async.cg.shared.global [%0],[%1],16,%2;"
                 :: "r"(d), "l"(src), "r"(sz));
}
#define CP_COMMIT()  asm volatile("cp.async.commit_group;")
#define CP_WAIT1()   asm volatile("cp.async.wait_group 1;")

// -------- pre: zero accumulators, deg = 1 (self loop) --------
__global__ void k_pre(int n) {
    int stride = gridDim.x * blockDim.x;
    int t0 = blockIdx.x * blockDim.x + threadIdx.x;
    for (int t = t0; t < n * HID; t += stride) g_agg1[t] = 0.f;
    for (int t = t0; t < n * H2;  t += stride) g_agg2[t] = 0.f;
    for (int t = t0; t < n;       t += stride) g_deg[t]  = 1.f;
}

// ======== mega: blocks [0,GB) gemm, blocks [GB,GB+DEGB) deg count ======
__global__ void __launch_bounds__(TPB)
k_mega(const float* __restrict__ x, const float* __restrict__ W1,
       const int* __restrict__ col, int n, int ne, int GB) {
    if (blockIdx.x >= GB) {
        int t0 = (blockIdx.x - GB) * TPB + threadIdx.x;
        int stride = DEGB * TPB;
        for (int e = t0; e < ne; e += stride)
            atomicAdd(&g_deg[__ldg(&col[e])], 1.0f);
        return;
    }

    extern __shared__ float4 smem[];
    float4* sX4 = smem;                 // S * NB*4
    float4* sW4 = smem + S * NB * 4;    // S * 64

    const int tid  = threadIdx.x;
    const int base = blockIdx.x * NB;
    const int sr   = tid >> 2;          // staging base row (0..31)
    const int c4   = tid & 3;           // staging float4 col

    unsigned long long acc0[HID / 2], acc1[HID / 2];
#pragma unroll
    for (int p = 0; p < HID / 2; p++) { acc0[p] = 0ull; acc1[p] = 0ull; }

    // ---- issue helper (inlined manually): chunk c into stage s ----
#define ISSUE(cc, ss)                                                        \
    do {                                                                     \
        float4* dx = &sX4[(ss) * NB * 4];                                    \
        _Pragma("unroll")                                                    \
        for (int i = 0; i < 8; i++) {                                        \
            int r  = sr + i * 32;                                            \
            int gn = base + r;                                               \
            cp16(&dx[r * 4 + (c4 ^ ((r >> 1) & 3))],                         \
                 (const float4*)(x + (size_t)gn * FIN + (cc) * KC) + c4,     \
                 gn < n);                                                    \
        }                                                                    \
        if (tid < 64)                                                        \
            cp16(&sW4[(ss) * 64 + tid],                                      \
                 (const float4*)W1 + (cc) * 64 + tid, true);                 \
        CP_COMMIT();                                                         \
    } while (0)

    ISSUE(0, 0);
    ISSUE(1, 1);

    const int r0 = tid, r1 = tid + TPB;
    const int sw = (r0 >> 1) & 3;       // same for r1 (=r0+128)

    for (int c = 0; c < NCHUNK; c++) {
        CP_WAIT1();            // chunk c resident
        __syncthreads();       // visible to all; prior compute done

        if (c + 2 < NCHUNK) { int s2 = (c + 2) % S; ISSUE(c + 2, s2); }
        else CP_COMMIT();      // keep group accounting uniform

        const int s = c % S;
        const float4* bx = &sX4[s * NB * 4];
        const ulonglong2* sWu = (const ulonglong2*)(&sW4[s * 64]);
#pragma unroll
        for (int kk = 0; kk < 4; kk++) {
            float4 xa = bx[r0 * 4 + (kk ^ sw)];
            float4 xb = bx[r1 * 4 + (kk ^ sw)];
            float ea[4] = {xa.x, xa.y, xa.z, xa.w};
            float eb[4] = {xb.x, xb.y, xb.z, xb.w};
#pragma unroll
            for (int e = 0; e < 4; e++) {
                int k = kk * 4 + e;
                unsigned long long xx0 = pack2(ea[e], ea[e]);
                unsigned long long xx1 = pack2(eb[e], eb[e]);
                const ulonglong2* wk = &sWu[k * 4];
#pragma unroll
                for (int p = 0; p < 4; p++) {
                    ulonglong2 w = wk[p];
                    ffma2(acc0[2 * p],     w.x, xx0);
                    ffma2(acc0[2 * p + 1], w.y, xx0);
                    ffma2(acc1[2 * p],     w.x, xx1);
                    ffma2(acc1[2 * p + 1], w.y, xx1);
                }
            }
        }
    }
#undef ISSUE

    int n0 = base + r0, n1 = base + r1;
    if (n0 < n) {
        float4* o = (float4*)(&g_xs[(size_t)n0 * HID]);
#pragma unroll
        for (int p = 0; p < HID / 4; p++) {
            float2 a = unpack2(acc0[2 * p]), b = unpack2(acc0[2 * p + 1]);
            o[p] = make_float4(a.x, a.y, b.x, b.y);
        }
    }
    if (n1 < n) {
        float4* o = (float4*)(&g_xs[(size_t)n1 * HID]);
#pragma unroll
        for (int p = 0; p < HID / 4; p++) {
            float2 a = unpack2(acc1[2 * p]), b = unpack2(acc1[2 * p + 1]);
            o[p] = make_float4(a.x, a.y, b.x, b.y);
        }
    }
}

// -------- finish: dinv = rsqrt(deg); xs *= dinv --------
__global__ void k_finish(int n) {
    int i = blockIdx.x * blockDim.x + threadIdx.x;
    if (i >= n) return;
    float d = rsqrtf(g_deg[i]);
    g_dinv[i] = d;
    float4* p = (float4*)(&g_xs[(size_t)i * HID]);
#pragma unroll
    for (int j = 0; j < HID / 4; j++) {
        float4 v = p[j];
        v.x *= d; v.y *= d; v.z *= d; v.w *= d;
        p[j] = v;
    }
}

// -------- layer-1 aggregation: 4-lane groups, 2 edges per group (ILP) -----
__global__ void k_agg1(const int* __restrict__ row,
                       const int* __restrict__ col, int ne) {
    int t = blockIdx.x * blockDim.x + threadIdx.x;
    int g = t >> 2, q = t & 3;
    int e0 = g * 2, e1 = e0 + 1;
    if (e0 >= ne) return;
    int r0 = __ldg(&row[e0]);
    int c0 = __ldg(&col[e0]);
    float4 v0 = *(const float4*)(&g_xs[(size_t)r0 * HID + q * 4]);
    if (e1 < ne) {
        int r1 = __ldg(&row[e1]);
        int c1 = __ldg(&col[e1]);
        float4 v1 = *(const float4*)(&g_xs[(size_t)r1 * HID + q * 4]);
        red_add_v4(&g_agg1[(size_t)c0 * HID + q * 4], v0);
        red_add_v4(&g_agg1[(size_t)c1 * HID + q * 4], v1);
    } else {
        red_add_v4(&g_agg1[(size_t)c0 * HID + q * 4], v0);
    }
}

// ---- h1 = relu(dinv*(agg1 + xs) + b1); hs = dinv * (h1 @ W2) ----
__global__ void k_h1(const float* __restrict__ b1,
                     const float* __restrict__ W2, int n) {
    __shared__ float sW2[HID * NC];
    __shared__ float sb1[HID];
    if (threadIdx.x < HID * NC) sW2[threadIdx.x] = W2[threadIdx.x];
    if (threadIdx.x < HID)      sb1[threadIdx.x] = b1[threadIdx.x];
    __syncthreads();

    int i = blockIdx.x * blockDim.x + threadIdx.x;
    if (i >= n) return;

    float d = g_dinv[i];
    float h[HID];
#pragma unroll
    for (int j = 0; j < HID; j++) {
        float v = d * (g_agg1[(size_t)i * HID + j] + g_xs[(size_t)i * HID + j]) + sb1[j];
        h[j] = v > 0.f ? v : 0.f;
    }
    float y[H2];
#pragma unroll
    for (int j = 0; j < H2; j++) y[j] = 0.f;
#pragma unroll
    for (int k = 0; k < HID; k++) {
        float hk = h[k];
#pragma unroll
        for (int j = 0; j < NC; j++) y[j] += hk * sW2[k * NC + j];
    }
    float4* o = (float4*)(&g_hs[(size_t)i * H2]);
    o[0] = make_float4(d * y[0], d * y[1], d * y[2], d * y[3]);
    o[1] = make_float4(d * y[4], d * y[5], d * y[6], 0.f);
}

// -------- layer-2 aggregation: 2-lane groups, 2 edges per group ----------
__global__ void k_agg2(const int* __restrict__ row,
                       const int* __restrict__ col, int ne) {
    int t = blockIdx.x * blockDim.x + threadIdx.x;
    int g = t >> 1, q = t & 1;
    int e0 = g * 2, e1 = e0 + 1;
    if (e0 >= ne) return;
    int r0 = __ldg(&row[e0]);
    int c0 = __ldg(&col[e0]);
    float4 v0 = *(const float4*)(&g_hs[(size_t)r0 * H2 + q * 4]);
    if (e1 < ne) {
        int r1 = __ldg(&row[e1]);
        int c1 = __ldg(&col[e1]);
        float4 v1 = *(const float4*)(&g_hs[(size_t)r1 * H2 + q * 4]);
        red_add_v4(&g_agg2[(size_t)c0 * H2 + q * 4], v0);
        red_add_v4(&g_agg2[(size_t)c1 * H2 + q * 4], v1);
    } else {
        red_add_v4(&g_agg2[(size_t)c0 * H2 + q * 4], v0);
    }
}

// ---- out = dinv*(agg2 + hs) + b2 ----
__global__ void k_out(float* __restrict__ out, const float* __restrict__ b2, int n) {
    int i = blockIdx.x * blockDim.x + threadIdx.x;
    if (i >= n) return;
    float d = g_dinv[i];
#pragma unroll
    for (int j = 0; j < NC; j++)
        out[(size_t)i * NC + j] =
            d * (g_agg2[(size_t)i * H2 + j] + g_hs[(size_t)i * H2 + j]) + __ldg(&b2[j]);
}

extern "C" void kernel_launch(void* const* d_in, const int* in_sizes, int n_in,
                              void* d_out, int out_size) {
    const float* x  = (const float*)d_in[0];
    const int*   ei = (const int*)  d_in[1];
    const float* W1 = (const float*)d_in[2];
    const float* b1 = (const float*)d_in[3];
    const float* W2 = (const float*)d_in[4];
    const float* b2 = (const float*)d_in[5];

    int n  = in_sizes[0] / FIN;
    int ne = in_sizes[1] / 2;
    const int* row = ei;
    const int* col = ei + ne;
    int GB = (n + NB - 1) / NB;   // 391 gemm blocks

    cudaFuncSetAttribute(k_mega, cudaFuncAttributeMaxDynamicSharedMemorySize, SMEM_DYN);

    k_pre   <<<148 * 8, 256>>>(n);
    k_mega  <<<GB + DEGB, TPB, SMEM_DYN>>>(x, W1, col, n, ne, GB);
    k_finish<<<(n + 255) / 256, 256>>>(n);
    k_agg1  <<<((ne * 2) + 255) / 256, 256>>>(row, col, ne);
    k_h1    <<<(n + 255) / 256, 256>>>(b1, W2, n);
    k_agg2  <<<(ne + 255) / 256, 256>>>(row, col, ne);
    k_out   <<<(n + 255) / 256, 256>>>((float*)d_out, b2, n);
}

// round 8
// speedup vs baseline: 1.4098x; 1.0422x over previous
#include <cuda_runtime.h>
#include <cuda_fp16.h>

#define N_MAX   100000
#define FIN     512
#define HID     16
#define NC      7
#define H2      8
#define NB      256            // nodes per gemm block
#define TPB     128            // threads per gemm block
#define KC      16             // k floats per chunk
#define NCHUNK  (FIN / KC)     // 32
#define S       3              // pipeline stages
#define DEGB    1024           // deg blocks appended to mega grid
#define SMEM_DYN ((S * (NB * 4 + 64)) * 16)

// -------- scratch (invariant: g_deg, g_agg1, g_agg2 zero at entry) --------
__device__ float    g_dinv[N_MAX];
__device__ float    g_deg [N_MAX];
__device__ float    g_xs  [N_MAX * HID];   // x @ W1 (fp32, pre-dinv)
__device__ unsigned g_xsh [N_MAX * 8];     // fp16x2: dinv * (x @ W1)
__device__ float    g_agg1[N_MAX * HID];
__device__ unsigned g_hsh [N_MAX * 4];     // fp16x2: dinv * (h1 @ W2)
__device__ float    g_agg2[N_MAX * H2];

__device__ __forceinline__ void red_add_v4(float* p, float4 v) {
    asm volatile("red.global.add.v4.f32 [%0], {%1,%2,%3,%4};"
                 :: "l"(p), "f"(v.x), "f"(v.y), "f"(v.z), "f"(v.w)
                 : "memory");
}
__device__ __forceinline__ unsigned long long pack2(float a, float b) {
    unsigned long long r;
    asm("mov.b64 %0,{%1,%2};" : "=l"(r) : "f"(a), "f"(b));
    return r;
}
__device__ __forceinline__ void ffma2(unsigned long long& d,
                                      unsigned long long a, unsigned long long b) {
    asm("fma.rn.f32x2 %0,%1,%2,%0;" : "+l"(d) : "l"(a), "l"(b));
}
__device__ __forceinline__ float2 unpack2(unsigned long long v) {
    float2 u;
    asm("mov.b64 {%0,%1},%2;" : "=f"(u.x), "=f"(u.y) : "l"(v));
    return u;
}
__device__ __forceinline__ void cp16(float4* dst_smem, const float4* src, bool pred) {
    unsigned d = (unsigned)__cvta_generic_to_shared(dst_smem);
    int sz = pred ? 16 : 0;
    asm volatile("cp.async.cg.shared.global [%0],[%1],16,%2;"
                 :: "r"(d), "l"(src), "r"(sz));
}
#define CP_COMMIT()  asm volatile("cp.async.commit_group;")
#define CP_WAIT1()   asm volatile("cp.async.wait_group 1;")

__device__ __forceinline__ unsigned h2pack(float a, float b) {
    __half2 h = __floats2half2_rn(a, b);
    return *(unsigned*)&h;
}
__device__ __forceinline__ float4 h4unpack(uint2 p) {
    float2 a = __half22float2(*(__half2*)&p.x);
    float2 b = __half22float2(*(__half2*)&p.y);
    return make_float4(a.x, a.y, b.x, b.y);
}

// ======== mega: blocks [0,GB) gemm, blocks [GB,GB+DEGB) deg count ======
__global__ void __launch_bounds__(TPB)
k_mega(const float* __restrict__ x, const float* __restrict__ W1,
       const int* __restrict__ col, int n, int ne, int GB) {
    if (blockIdx.x >= GB) {
        int t0 = (blockIdx.x - GB) * TPB + threadIdx.x;
        int stride = DEGB * TPB;
        for (int e = t0; e < ne; e += stride)
            atomicAdd(&g_deg[__ldg(&col[e])], 1.0f);
        return;
    }

    extern __shared__ float4 smem[];
    float4* sX4 = smem;                 // S * NB*4
    float4* sW4 = smem + S * NB * 4;    // S * 64

    const int tid  = threadIdx.x;
    const int base = blockIdx.x * NB;
    const int sr   = tid >> 2;
    const int c4   = tid & 3;

    unsigned long long acc0[HID / 2], acc1[HID / 2];
#pragma unroll
    for (int p = 0; p < HID / 2; p++) { acc0[p] = 0ull; acc1[p] = 0ull; }

#define ISSUE(cc, ss)                                                        \
    do {                                                                     \
        float4* dx = &sX4[(ss) * NB * 4];                                    \
        _Pragma("unroll")                                                    \
        for (int i = 0; i < 8; i++) {                                        \
            int r  = sr + i * 32;                                            \
            int gn = base + r;                                               \
            cp16(&dx[r * 4 + (c4 ^ ((r >> 1) & 3))],                         \
                 (const float4*)(x + (size_t)gn * FIN + (cc) * KC) + c4,     \
                 gn < n);                                                    \
        }                                                                    \
        if (tid < 64)                                                        \
            cp16(&sW4[(ss) * 64 + tid],                                      \
                 (const float4*)W1 + (cc) * 64 + tid, true);                 \
        CP_COMMIT();                                                         \
    } while (0)

    ISSUE(0, 0);
    ISSUE(1, 1);

    const int r0 = tid, r1 = tid + TPB;
    const int sw = (r0 >> 1) & 3;

    for (int c = 0; c < NCHUNK; c++) {
        CP_WAIT1();
        __syncthreads();

        if (c + 2 < NCHUNK) { int s2 = (c + 2) % S; ISSUE(c + 2, s2); }
        else CP_COMMIT();

        const int s = c % S;
        const float4* bx = &sX4[s * NB * 4];
        const ulonglong2* sWu = (const ulonglong2*)(&sW4[s * 64]);
#pragma unroll
        for (int kk = 0; kk < 4; kk++) {
            float4 xa = bx[r0 * 4 + (kk ^ sw)];
            float4 xb = bx[r1 * 4 + (kk ^ sw)];
            float ea[4] = {xa.x, xa.y, xa.z, xa.w};
            float eb[4] = {xb.x, xb.y, xb.z, xb.w};
#pragma unroll
            for (int e = 0; e < 4; e++) {
                int k = kk * 4 + e;
                unsigned long long xx0 = pack2(ea[e], ea[e]);
                unsigned long long xx1 = pack2(eb[e], eb[e]);
                const ulonglong2* wk = &sWu[k * 4];
#pragma unroll
                for (int p = 0; p < 4; p++) {
                    ulonglong2 w = wk[p];
                    ffma2(acc0[2 * p],     w.x, xx0);
                    ffma2(acc0[2 * p + 1], w.y, xx0);
                    ffma2(acc1[2 * p],     w.x, xx1);
                    ffma2(acc1[2 * p + 1], w.y, xx1);
                }
            }
        }
    }
#undef ISSUE

    int n0 = base + r0, n1 = base + r1;
    if (n0 < n) {
        float4* o = (float4*)(&g_xs[(size_t)n0 * HID]);
#pragma unroll
        for (int p = 0; p < HID / 4; p++) {
            float2 a = unpack2(acc0[2 * p]), b = unpack2(acc0[2 * p + 1]);
            o[p] = make_float4(a.x, a.y, b.x, b.y);
        }
    }
    if (n1 < n) {
        float4* o = (float4*)(&g_xs[(size_t)n1 * HID]);
#pragma unroll
        for (int p = 0; p < HID / 4; p++) {
            float2 a = unpack2(acc1[2 * p]), b = unpack2(acc1[2 * p + 1]);
            o[p] = make_float4(a.x, a.y, b.x, b.y);
        }
    }
}

// ---- finish: dinv = rsqrt(deg+1); xsh = fp16(dinv * xs) ----
__global__ void k_finish(int n) {
    int i = blockIdx.x * blockDim.x + threadIdx.x;
    if (i >= n) return;
    float d = rsqrtf(g_deg[i] + 1.0f);
    g_dinv[i] = d;
    const float4* p = (const float4*)(&g_xs[(size_t)i * HID]);
    uint4 o[2];
#pragma unroll
    for (int j = 0; j < 2; j++) {
        float4 a = p[j * 2], b = p[j * 2 + 1];
        o[j] = make_uint4(h2pack(d * a.x, d * a.y), h2pack(d * a.z, d * a.w),
                          h2pack(d * b.x, d * b.y), h2pack(d * b.z, d * b.w));
    }
    uint4* q = (uint4*)(&g_xsh[(size_t)i * 8]);
    q[0] = o[0]; q[1] = o[1];
}

// ---- layer-1 aggregation: fp16 gather, fp32 red; 4 lanes / 2 edges ----
__global__ void k_agg1(const int* __restrict__ row,
                       const int* __restrict__ col, int ne) {
    int t = blockIdx.x * blockDim.x + threadIdx.x;
    int g = t >> 2, q = t & 3;
    int e0 = g * 2, e1 = e0 + 1;
    if (e0 >= ne) return;
    int r0 = __ldg(&row[e0]);
    int c0 = __ldg(&col[e0]);
    uint2 p0 = *(const uint2*)(&g_xsh[(size_t)r0 * 8 + q * 2]);
    if (e1 < ne) {
        int r1 = __ldg(&row[e1]);
        int c1 = __ldg(&col[e1]);
        uint2 p1 = *(const uint2*)(&g_xsh[(size_t)r1 * 8 + q * 2]);
        red_add_v4(&g_agg1[(size_t)c0 * HID + q * 4], h4unpack(p0));
        red_add_v4(&g_agg1[(size_t)c1 * HID + q * 4], h4unpack(p1));
    } else {
        red_add_v4(&g_agg1[(size_t)c0 * HID + q * 4], h4unpack(p0));
    }
}

// ---- h1 = relu(dinv*(agg1 + xsh) + b1); hsh = fp16(dinv*(h1 @ W2));
//      restores agg1 to zero ----
__global__ void k_h1(const float* __restrict__ b1,
                     const float* __restrict__ W2, int n) {
    __shared__ float sW2[HID * NC];
    __shared__ float sb1[HID];
    if (threadIdx.x < HID * NC) sW2[threadIdx.x] = W2[threadIdx.x];
    if (threadIdx.x < HID)      sb1[threadIdx.x] = b1[threadIdx.x];
    __syncthreads();

    int i = blockIdx.x * blockDim.x + threadIdx.x;
    if (i >= n) return;

    float d = g_dinv[i];
    const uint4* xq = (const uint4*)(&g_xsh[(size_t)i * 8]);
    uint4 x0 = xq[0], x1 = xq[1];
    float xsv[HID];
    { float4 a = h4unpack(make_uint2(x0.x, x0.y));
      float4 b = h4unpack(make_uint2(x0.z, x0.w));
      float4 c = h4unpack(make_uint2(x1.x, x1.y));
      float4 e = h4unpack(make_uint2(x1.z, x1.w));
      xsv[0]=a.x; xsv[1]=a.y; xsv[2]=a.z;  xsv[3]=a.w;
      xsv[4]=b.x; xsv[5]=b.y; xsv[6]=b.z;  xsv[7]=b.w;
      xsv[8]=c.x; xsv[9]=c.y; xsv[10]=c.z; xsv[11]=c.w;
      xsv[12]=e.x; xsv[13]=e.y; xsv[14]=e.z; xsv[15]=e.w; }

    float4* ag = (float4*)(&g_agg1[(size_t)i * HID]);
    float h[HID];
#pragma unroll
    for (int j4 = 0; j4 < 4; j4++) {
        float4 a = ag[j4];
        float av[4] = {a.x, a.y, a.z, a.w};
#pragma unroll
        for (int u = 0; u < 4; u++) {
            int j = j4 * 4 + u;
            float v = d * (av[u] + xsv[j]) + sb1[j];
            h[j] = v > 0.f ? v : 0.f;
        }
        ag[j4] = make_float4(0.f, 0.f, 0.f, 0.f);   // restore zero
    }

    float y[H2];
#pragma unroll
    for (int j = 0; j < H2; j++) y[j] = 0.f;
#pragma unroll
    for (int k = 0; k < HID; k++) {
        float hk = h[k];
#pragma unroll
        for (int j = 0; j < NC; j++) y[j] += hk * sW2[k * NC + j];
    }
    uint4* o = (uint4*)(&g_hsh[(size_t)i * 4]);
    *o = make_uint4(h2pack(d * y[0], d * y[1]), h2pack(d * y[2], d * y[3]),
                    h2pack(d * y[4], d * y[5]), h2pack(d * y[6], 0.f));
}

// ---- layer-2 aggregation: fp16 gather; 2 lanes / 2 edges ----
__global__ void k_agg2(const int* __restrict__ row,
                       const int* __restrict__ col, int ne) {
    int t = blockIdx.x * blockDim.x + threadIdx.x;
    int g = t >> 1, q = t & 1;
    int e0 = g * 2, e1 = e0 + 1;
    if (e0 >= ne) return;
    int r0 = __ldg(&row[e0]);
    int c0 = __ldg(&col[e0]);
    uint2 p0 = *(const uint2*)(&g_hsh[(size_t)r0 * 4 + q * 2]);
    if (e1 < ne) {
        int r1 = __ldg(&row[e1]);
        int c1 = __ldg(&col[e1]);
        uint2 p1 = *(const uint2*)(&g_hsh[(size_t)r1 * 4 + q * 2]);
        red_add_v4(&g_agg2[(size_t)c0 * H2 + q * 4], h4unpack(p0));
        red_add_v4(&g_agg2[(size_t)c1 * H2 + q * 4], h4unpack(p1));
    } else {
        red_add_v4(&g_agg2[(size_t)c0 * H2 + q * 4], h4unpack(p0));
    }
}

// ---- out = dinv*(agg2 + hsh) + b2; restores agg2 and deg to zero ----
__global__ void k_out(float* __restrict__ out, const float* __restrict__ b2, int n) {
    int i = blockIdx.x * blockDim.x + threadIdx.x;
    if (i >= n) return;
    float d = g_dinv[i];
    uint4 hq = *(const uint4*)(&g_hsh[(size_t)i * 4]);
    float4 ha = h4unpack(make_uint2(hq.x, hq.y));
    float4 hb = h4unpack(make_uint2(hq.z, hq.w));
    float hs[8] = {ha.x, ha.y, ha.z, ha.w, hb.x, hb.y, hb.z, hb.w};

    float4* ag = (float4*)(&g_agg2[(size_t)i * H2]);
    float4 a0 = ag[0], a1 = ag[1];
    float av[8] = {a0.x, a0.y, a0.z, a0.w, a1.x, a1.y, a1.z, a1.w};
#pragma unroll
    for (int j = 0; j < NC; j++)
        out[(size_t)i * NC + j] = d * (av[j] + hs[j]) + __ldg(&b2[j]);

    ag[0] = make_float4(0.f, 0.f, 0.f, 0.f);    // restore zero
    ag[1] = make_float4(0.f, 0.f, 0.f, 0.f);
    g_deg[i] = 0.f;
}

extern "C" void kernel_launch(void* const* d_in, const int* in_sizes, int n_in,
                              void* d_out, int out_size) {
    const float* x  = (const float*)d_in[0];
    const int*   ei = (const int*)  d_in[1];
    const float* W1 = (const float*)d_in[2];
    const float* b1 = (const float*)d_in[3];
    const float* W2 = (const float*)d_in[4];
    const float* b2 = (const float*)d_in[5];

    int n  = in_sizes[0] / FIN;
    int ne = in_sizes[1] / 2;
    const int* row = ei;
    const int* col = ei + ne;
    int GB = (n + NB - 1) / NB;

    cudaFuncSetAttribute(k_mega, cudaFuncAttributeMaxDynamicSharedMemorySize, SMEM_DYN);

    k_mega  <<<GB + DEGB, TPB, SMEM_DYN>>>(x, W1, col, n, ne, GB);
    k_finish<<<(n + 255) / 256, 256>>>(n);
    k_agg1  <<<((ne * 2) + 255) / 256, 256>>>(row, col, ne);
    k_h1    <<<(n + 255) / 256, 256>>>(b1, W2, n);
    k_agg2  <<<(ne + 255) / 256, 256>>>(row, col, ne);
    k_out   <<<(n + 255) / 256, 256>>>((float*)d_out, b2, n);
}